// round 1
// baseline (speedup 1.0000x reference)
#include <cuda_runtime.h>
#include <cstdint>

// out[b, g, k, c] = textures[b, group_idx[g, k], c]
// B=2, T=1e6, C=16 (fp32), G=500000, K=9. mesh_ids (d_in[0]) unused by reference.
//
// One thread per float4 (C=16 -> 4 x float4 per texel row).
//   i in [0, GK*4): c4 = i & 3, gk = i >> 2
//   writes: fully coalesced STG.128 over [G,K,C] contiguous layout
//   reads:  4 consecutive lanes read one 64B texel row (LDG.128 x4, 2 sectors)
//   batch in grid.y (per-batch base pointers, no 64-bit div in the hot path)

__global__ void __launch_bounds__(256)
tmscnn_gather_kernel(const float4* __restrict__ tex,     // [B, T*C/4]
                     const int*    __restrict__ gidx,    // [G*K]
                     float4*       __restrict__ out,     // [B, G*K*4]
                     int total_f4,                       // G*K*4
                     long long tex_batch_stride_f4,      // T*C/4
                     long long out_batch_stride_f4)      // G*K*4
{
    int i = blockIdx.x * blockDim.x + threadIdx.x;
    if (i >= total_f4) return;

    int b  = blockIdx.y;
    int gk = i >> 2;
    int c4 = i & 3;

    int t = __ldg(gidx + gk);

    const float4* tex_b = tex + (long long)b * tex_batch_stride_f4;
    float4*       out_b = out + (long long)b * out_batch_stride_f4;

    out_b[i] = __ldg(tex_b + (long long)t * 4 + c4);
}

extern "C" void kernel_launch(void* const* d_in, const int* in_sizes, int n_in,
                              void* d_out, int out_size)
{
    // metadata order: mesh_ids [B] int32, textures [B,T,C] f32, group_idx [G,K] int32
    const float* textures = (const float*)d_in[1];
    const int*   gidx     = (const int*)d_in[2];
    float*       out      = (float*)d_out;

    int B  = in_sizes[0];             // 2
    int GK = in_sizes[2];             // G*K = 4,500,000
    long long TC = (long long)in_sizes[1] / B;   // T*C = 16,000,000

    int total_f4 = GK * 4;            // 18,000,000 threads per batch
    long long tex_stride_f4 = TC / 4; // 4,000,000
    long long out_stride_f4 = (long long)GK * 4;

    dim3 block(256);
    dim3 grid((total_f4 + 255) / 256, B);

    tmscnn_gather_kernel<<<grid, block>>>(
        (const float4*)textures, gidx, (float4*)out,
        total_f4, tex_stride_f4, out_stride_f4);
}

// round 2
// speedup vs baseline: 1.0212x; 1.0212x over previous
#include <cuda_runtime.h>
#include <cstdint>

// out[b, g, k, c] = textures[b, group_idx[g, k], c]
// B=2, T=1e6, C=16 (fp32), G=500000, K=9.
//
// R2 change: output stores use __stcs (evict-first streaming) so the 576 MB
// write stream does not evict the 64 MB texture working set from L2.
// Gather reads (avg 4.5x reuse per texel) should then mostly hit L2,
// cutting DRAM read traffic ~430MB -> ~130MB.

__global__ void __launch_bounds__(256)
tmscnn_gather_kernel(const float4* __restrict__ tex,     // [B, T*C/4]
                     const int*    __restrict__ gidx,    // [G*K]
                     float4*       __restrict__ out,     // [B, G*K*4]
                     int total_f4,                       // G*K*4
                     long long tex_batch_stride_f4,      // T*C/4
                     long long out_batch_stride_f4)      // G*K*4
{
    int i = blockIdx.x * blockDim.x + threadIdx.x;
    if (i >= total_f4) return;

    int b  = blockIdx.y;
    int gk = i >> 2;
    int c4 = i & 3;

    int t = __ldg(gidx + gk);

    const float4* tex_b = tex + (long long)b * tex_batch_stride_f4;
    float4*       out_b = out + (long long)b * out_batch_stride_f4;

    float4 v = __ldg(tex_b + (long long)t * 4 + c4);
    __stcs(out_b + i, v);   // streaming store: evict-first in L2
}

extern "C" void kernel_launch(void* const* d_in, const int* in_sizes, int n_in,
                              void* d_out, int out_size)
{
    // metadata order: mesh_ids [B] int32, textures [B,T,C] f32, group_idx [G,K] int32
    const float* textures = (const float*)d_in[1];
    const int*   gidx     = (const int*)d_in[2];
    float*       out      = (float*)d_out;

    int B  = in_sizes[0];             // 2
    int GK = in_sizes[2];             // G*K = 4,500,000
    long long TC = (long long)in_sizes[1] / B;   // T*C = 16,000,000

    int total_f4 = GK * 4;            // 18,000,000 threads per batch
    long long tex_stride_f4 = TC / 4; // 4,000,000
    long long out_stride_f4 = (long long)GK * 4;

    dim3 block(256);
    dim3 grid((total_f4 + 255) / 256, B);

    tmscnn_gather_kernel<<<grid, block>>>(
        (const float4*)textures, gidx, (float4*)out,
        total_f4, tex_stride_f4, out_stride_f4);
}

// round 3
// speedup vs baseline: 1.1812x; 1.1567x over previous
#include <cuda_runtime.h>
#include <cstdint>

// out[b, g, k, c] = textures[b, group_idx[g, k], c]
// B=2, T=1e6, C=16 (fp32), G=500000, K=9.
//
// R3: latency/MLP fix. R2 ncu showed nothing saturated (DRAM 56%, L2 35%,
// issue 15%) => latency-bound with gather MLP=1 per thread. Each thread now
// processes U=8 elements grid-strided in 3 phases:
//   phase 1: 8 independent index loads
//   phase 2: 8 independent texel float4 gathers
//   phase 3: 8 streaming stores
// Coalescing identical to R2 (stride is the whole grid). Gather MLP_eff ~8.

#define U 8

__global__ void __launch_bounds__(256)
tmscnn_gather_kernel(const float4* __restrict__ tex,     // [B, T*C/4]
                     const int*    __restrict__ gidx,    // [G*K]
                     float4*       __restrict__ out,     // [B, G*K*4]
                     int total_f4,                       // G*K*4
                     long long tex_batch_stride_f4,      // T*C/4
                     long long out_batch_stride_f4)      // G*K*4
{
    const int stride = gridDim.x * blockDim.x;
    const int i0 = blockIdx.x * blockDim.x + threadIdx.x;
    const int b = blockIdx.y;

    const float4* tex_b = tex + (long long)b * tex_batch_stride_f4;
    float4*       out_b = out + (long long)b * out_batch_stride_f4;

    int   ii[U];
    int   tt[U];
    float4 vv[U];

    // Phase 1: independent index loads
    #pragma unroll
    for (int u = 0; u < U; u++) {
        ii[u] = i0 + u * stride;
        tt[u] = 0;
        if (ii[u] < total_f4)
            tt[u] = __ldg(gidx + (ii[u] >> 2));
    }

    // Phase 2: independent texel gathers (MLP = U)
    #pragma unroll
    for (int u = 0; u < U; u++) {
        if (ii[u] < total_f4)
            vv[u] = __ldg(tex_b + (long long)tt[u] * 4 + (ii[u] & 3));
    }

    // Phase 3: streaming stores
    #pragma unroll
    for (int u = 0; u < U; u++) {
        if (ii[u] < total_f4)
            __stcs(out_b + ii[u], vv[u]);
    }
}

extern "C" void kernel_launch(void* const* d_in, const int* in_sizes, int n_in,
                              void* d_out, int out_size)
{
    // metadata order: mesh_ids [B] int32, textures [B,T,C] f32, group_idx [G,K] int32
    const float* textures = (const float*)d_in[1];
    const int*   gidx     = (const int*)d_in[2];
    float*       out      = (float*)d_out;

    int B  = in_sizes[0];             // 2
    int GK = in_sizes[2];             // G*K = 4,500,000
    long long TC = (long long)in_sizes[1] / B;   // T*C = 16,000,000

    int total_f4 = GK * 4;            // 18,000,000 elements per batch
    long long tex_stride_f4 = TC / 4; // 4,000,000
    long long out_stride_f4 = (long long)GK * 4;

    // Each thread handles U elements, grid-strided.
    int threads_needed = (total_f4 + U - 1) / U;
    dim3 block(256);
    dim3 grid((threads_needed + 255) / 256, B);

    tmscnn_gather_kernel<<<grid, block>>>(
        (const float4*)textures, gidx, (float4*)out,
        total_f4, tex_stride_f4, out_stride_f4);
}